// round 15
// baseline (speedup 1.0000x reference)
#include <cuda_runtime.h>
#include <cuda_bf16.h>
#include <cstdint>

#define N_TOK 2048
#define K_TOK 128
#define D_DIM 768
#define H_DIM 512
#define M_ALL 2176   // 2048 img rows + 128 txt rows
#define NSPLIT 8
#define KSPLIT_D 384 // K per proj split

// ---------------- scratch (device globals; no allocation allowed) ----------------
__device__ __align__(16) __nv_bfloat16 g_Ahi[M_ALL * D_DIM];
__device__ __align__(16) __nv_bfloat16 g_Alo[M_ALL * D_DIM];
__device__ __align__(16) __nv_bfloat16 g_Bhi[2 * H_DIM * D_DIM];  // [half][n][k] = W1^T
__device__ __align__(16) __nv_bfloat16 g_Blo[2 * H_DIM * D_DIM];
__device__ float g_imgP[2 * N_TOK * H_DIM];        // split-K partials [ks][n][h]
__device__ float g_txtP[2 * H_DIM * K_TOK];        // split-K partials [ks][h][k] (+b1 in ks0)
__device__ float g_part[NSPLIT * N_TOK * K_TOK];   // fused h-split partials
__device__ unsigned int g_cnt[64];                 // per-n-group completion counters (init 0)

typedef unsigned long long u64;

// ---------------- packed f32x2 helpers ----------------
__device__ __forceinline__ u64 pack2(float lo, float hi) {
    u64 r; asm("mov.b64 %0, {%1, %2};" : "=l"(r) : "f"(lo), "f"(hi)); return r;
}
__device__ __forceinline__ void unpack2(u64 v, float& lo, float& hi) {
    asm("mov.b64 {%0, %1}, %2;" : "=f"(lo), "=f"(hi) : "l"(v));
}
__device__ __forceinline__ void fma2(u64& d, u64 a, u64 b) {
    asm("fma.rn.f32x2 %0, %1, %2, %0;" : "+l"(d) : "l"(a), "l"(b));
}
__device__ __forceinline__ u64 add2(u64 a, u64 b) {
    u64 r; asm("add.rn.f32x2 %0, %1, %2;" : "=l"(r) : "l"(a), "l"(b)); return r;
}
__device__ __forceinline__ u64 relu2(u64 v) {
    float lo, hi; unpack2(v, lo, hi);
    return pack2(fmaxf(lo, 0.f), fmaxf(hi, 0.f));
}
__device__ __forceinline__ float4 f4add(float4 a, float4 b) {
    return make_float4(a.x + b.x, a.y + b.y, a.z + b.z, a.w + b.w);
}

// ---------------- portable HMMA + ldmatrix (plain sm_103 target) ----------------
__device__ __forceinline__ void mma_bf16(float* c, const uint32_t* a, const uint32_t* b) {
    asm("mma.sync.aligned.m16n8k16.row.col.f32.bf16.bf16.f32 "
        "{%0,%1,%2,%3}, {%4,%5,%6,%7}, {%8,%9}, {%0,%1,%2,%3};"
        : "+f"(c[0]), "+f"(c[1]), "+f"(c[2]), "+f"(c[3])
        : "r"(a[0]), "r"(a[1]), "r"(a[2]), "r"(a[3]), "r"(b[0]), "r"(b[1]));
}
__device__ __forceinline__ void ldmat_x4(uint32_t* r, uint32_t addr) {
    asm volatile("ldmatrix.sync.aligned.m8n8.x4.shared.b16 {%0,%1,%2,%3}, [%4];"
        : "=r"(r[0]), "=r"(r[1]), "=r"(r[2]), "=r"(r[3]) : "r"(addr));
}
__device__ __forceinline__ uint32_t smem_u32(const void* p) {
    uint32_t a;
    asm("{ .reg .u64 t; cvta.to.shared.u64 t, %1; cvt.u32.u64 %0, t; }" : "=r"(a) : "l"(p));
    return a;
}

// ============ merged conversion: A (fp32->bf16 hi/lo) + B (transpose + hi/lo) ============
__global__ __launch_bounds__(256) void conv_AB(
    const float* __restrict__ img, const float* __restrict__ txt,
    const float* __restrict__ W1)
{
    __shared__ float ts[32][33];
    if (blockIdx.x < 1632) {
        const int i4 = blockIdx.x * 256 + threadIdx.x;
        const int row = i4 / 192;
        const int col4 = (i4 - row * 192) * 4;
        const float4 v = (row < N_TOK)
            ? *(const float4*)&img[row * D_DIM + col4]
            : *(const float4*)&txt[(row - N_TOK) * D_DIM + col4];
        const float xs[4] = {v.x, v.y, v.z, v.w};
        unsigned short hb[4], lb[4];
        #pragma unroll
        for (int j = 0; j < 4; j++) {
            __nv_bfloat16 h = __float2bfloat16(xs[j]);
            __nv_bfloat16 l = __float2bfloat16(xs[j] - __bfloat162float(h));
            hb[j] = __bfloat16_as_ushort(h);
            lb[j] = __bfloat16_as_ushort(l);
        }
        const int e = row * D_DIM + col4;
        *(uint2*)(g_Ahi + e) = make_uint2(hb[0] | (hb[1] << 16), hb[2] | (hb[3] << 16));
        *(uint2*)(g_Alo + e) = make_uint2(lb[0] | (lb[1] << 16), lb[2] | (lb[3] << 16));
    } else {
        const int bb = blockIdx.x - 1632;            // 0..767
        const int half = bb / 384;
        const int k0 = ((bb - half * 384) >> 4) * 32;
        const int n0 = (bb & 15) * 32;
        const float* __restrict__ W = W1 + half * (D_DIM * H_DIM);
        const int r  = threadIdx.x >> 3;
        const int c4 = (threadIdx.x & 7) * 4;
        const float4 v = *(const float4*)&W[(k0 + r) * H_DIM + n0 + c4];
        ts[r][c4 + 0] = v.x; ts[r][c4 + 1] = v.y; ts[r][c4 + 2] = v.z; ts[r][c4 + 3] = v.w;
        __syncthreads();
        unsigned short hb[4], lb[4];
        #pragma unroll
        for (int j = 0; j < 4; j++) {
            const float x = ts[c4 + j][r];
            __nv_bfloat16 h = __float2bfloat16(x);
            __nv_bfloat16 l = __float2bfloat16(x - __bfloat162float(h));
            hb[j] = __bfloat16_as_ushort(h);
            lb[j] = __bfloat16_as_ushort(l);
        }
        const int e = half * (H_DIM * D_DIM) + (n0 + r) * D_DIM + k0 + c4;
        *(uint2*)(g_Bhi + e) = make_uint2(hb[0] | (hb[1] << 16), hb[2] | (hb[3] << 16));
        *(uint2*)(g_Blo + e) = make_uint2(lb[0] | (lb[1] << 16), lb[2] | (lb[3] << 16));
    }
}

// ============ HMMA projection GEMM — split-K x2, 2 CTAs/SM ============
#define KC 32
#define A_ROWSTRIDE 80           // bytes (40 bf16)
#define A_BUFSTRIDE (128 * 80)   // 10240
#define B_BUFSTRIDE (64 * 80)    // 5120
#define OFF_AHI 0
#define OFF_ALO 20480
#define OFF_BHI 40960
#define OFF_BLO 51200
#define PROJ_SMEM 61440

__global__ __launch_bounds__(256, 2) void mma_proj(const float* __restrict__ b1)
{
    extern __shared__ char smem[];
    const uint32_t sb = smem_u32(smem);

    const int t    = threadIdx.x;
    const int lane = t & 31;
    const int warp = t >> 5;
    const int wm   = warp >> 1;
    const int wn   = warp & 1;
    const int g    = lane >> 2;
    const int t2   = (lane & 3) << 1;

    const int a_lrow = lane & 15;
    const int a_k16  = (lane >> 4) << 4;
    const int b_lrow = (lane & 7) + ((lane >> 4) << 3);
    const int b_k16  = ((lane >> 3) & 1) << 4;

    const int tile = blockIdx.x >> 1;
    const int ks   = blockIdx.x & 1;
    const int kofs = ks * KSPLIT_D;
    const int mt = tile >> 3, nt = tile & 7;
    const int m0 = mt * 128, n0 = nt * 64;
    const bool is_txt = (mt == 16);
    const __nv_bfloat16* __restrict__ Bh = g_Bhi + (is_txt ? H_DIM * D_DIM : 0);
    const __nv_bfloat16* __restrict__ Bl = g_Blo + (is_txt ? H_DIM * D_DIM : 0);

    const int arow0 = t >> 2,           abyte0 = (t & 3) << 4;
    const int arow1 = (t + 256) >> 2,   abyte1 = abyte0;
    const int brow  = t >> 2,           bbyte  = (t & 3) << 4;
    const int eA0 = (m0 + arow0) * D_DIM + kofs + (abyte0 >> 1);
    const int eA1 = (m0 + arow1) * D_DIM + kofs + (abyte1 >> 1);
    const int eB  = (n0 + brow) * D_DIM + kofs + (bbyte >> 1);

    float acc[2][4][4];
    #pragma unroll
    for (int i = 0; i < 2; i++)
        #pragma unroll
        for (int j = 0; j < 4; j++)
            #pragma unroll
            for (int p = 0; p < 4; p++) acc[i][j][p] = 0.f;

    {
        *(float4*)(smem + OFF_AHI + arow0 * A_ROWSTRIDE + abyte0) = *(const float4*)(g_Ahi + eA0);
        *(float4*)(smem + OFF_AHI + arow1 * A_ROWSTRIDE + abyte1) = *(const float4*)(g_Ahi + eA1);
        *(float4*)(smem + OFF_ALO + arow0 * A_ROWSTRIDE + abyte0) = *(const float4*)(g_Alo + eA0);
        *(float4*)(smem + OFF_ALO + arow1 * A_ROWSTRIDE + abyte1) = *(const float4*)(g_Alo + eA1);
        *(float4*)(smem + OFF_BHI + brow * A_ROWSTRIDE + bbyte)   = *(const float4*)(Bh + eB);
        *(float4*)(smem + OFF_BLO + brow * A_ROWSTRIDE + bbyte)   = *(const float4*)(Bl + eB);
    }
    __syncthreads();

    const int NCHUNK = KSPLIT_D / KC;  // 12
    for (int kc = 0; kc < NCHUNK; kc++) {
        const int buf = kc & 1;

        float4 vah0, vah1, val0, val1, vbh, vbl;
        if (kc + 1 < NCHUNK) {
            const int k0 = (kc + 1) * KC;
            vah0 = *(const float4*)(g_Ahi + eA0 + k0);
            vah1 = *(const float4*)(g_Ahi + eA1 + k0);
            val0 = *(const float4*)(g_Alo + eA0 + k0);
            val1 = *(const float4*)(g_Alo + eA1 + k0);
            vbh  = *(const float4*)(Bh + eB + k0);
            vbl  = *(const float4*)(Bl + eB + k0);
        }

        const uint32_t aHiBase = sb + OFF_AHI + buf * A_BUFSTRIDE;
        const uint32_t bHiBase = sb + OFF_BHI + buf * B_BUFSTRIDE;

        #pragma unroll
        for (int kk = 0; kk < 2; kk++) {
            const int kbb = kk * 32;
            uint32_t ah[2][4], al[2][4], bh[2][4], bl[2][4];
            #pragma unroll
            for (int ma = 0; ma < 2; ma++) {
                const uint32_t ra = aHiBase
                    + (uint32_t)((wm * 32 + ma * 16 + a_lrow) * A_ROWSTRIDE + kbb + a_k16);
                ldmat_x4(ah[ma], ra);
                ldmat_x4(al[ma], ra + (OFF_ALO - OFF_AHI));
            }
            #pragma unroll
            for (int np = 0; np < 2; np++) {
                const uint32_t rb = bHiBase
                    + (uint32_t)((wn * 32 + np * 16 + b_lrow) * A_ROWSTRIDE + kbb + b_k16);
                ldmat_x4(bh[np], rb);
                ldmat_x4(bl[np], rb + (OFF_BLO - OFF_BHI));
            }
            #pragma unroll
            for (int ma = 0; ma < 2; ma++)
                #pragma unroll
                for (int na = 0; na < 4; na++) {
                    const uint32_t* bhp = &bh[na >> 1][(na & 1) * 2];
                    const uint32_t* blp = &bl[na >> 1][(na & 1) * 2];
                    mma_bf16(acc[ma][na], ah[ma], bhp);
                    mma_bf16(acc[ma][na], ah[ma], blp);
                    mma_bf16(acc[ma][na], al[ma], bhp);
                }
        }

        if (kc + 1 < NCHUNK) {
            const int so = (buf ^ 1);
            *(float4*)(smem + OFF_AHI + so * A_BUFSTRIDE + arow0 * A_ROWSTRIDE + abyte0) = vah0;
            *(float4*)(smem + OFF_AHI + so * A_BUFSTRIDE + arow1 * A_ROWSTRIDE + abyte1) = vah1;
            *(float4*)(smem + OFF_ALO + so * A_BUFSTRIDE + arow0 * A_ROWSTRIDE + abyte0) = val0;
            *(float4*)(smem + OFF_ALO + so * A_BUFSTRIDE + arow1 * A_ROWSTRIDE + abyte1) = val1;
            *(float4*)(smem + OFF_BHI + so * B_BUFSTRIDE + brow * A_ROWSTRIDE + bbyte) = vbh;
            *(float4*)(smem + OFF_BLO + so * B_BUFSTRIDE + brow * A_ROWSTRIDE + bbyte) = vbl;
        }
        __syncthreads();
    }

    float* imgP = g_imgP + ks * (N_TOK * H_DIM);
    float* txtP = g_txtP + ks * (H_DIM * K_TOK);
    #pragma unroll
    for (int ma = 0; ma < 2; ma++) {
        const int lr0 = wm * 32 + ma * 16 + g;
        #pragma unroll
        for (int na = 0; na < 4; na++) {
            const int n = n0 + wn * 32 + na * 8 + t2;
            if (!is_txt) {
                *(float2*)&imgP[(m0 + lr0) * H_DIM + n] =
                    make_float2(acc[ma][na][0], acc[ma][na][1]);
                *(float2*)&imgP[(m0 + lr0 + 8) * H_DIM + n] =
                    make_float2(acc[ma][na][2], acc[ma][na][3]);
            } else {
                const float bb0 = ks ? 0.f : __ldg(&b1[n]);
                const float bb1 = ks ? 0.f : __ldg(&b1[n + 1]);
                txtP[n * K_TOK + lr0]           = acc[ma][na][0] + bb0;
                txtP[(n + 1) * K_TOK + lr0]     = acc[ma][na][1] + bb1;
                txtP[n * K_TOK + lr0 + 8]       = acc[ma][na][2] + bb0;
                txtP[(n + 1) * K_TOK + lr0 + 8] = acc[ma][na][3] + bb1;
            }
        }
    }
}

// ============ fused relu-dot + in-kernel combine (threadfence reduction) ============
// part[hs][n][k] = sum_{h in 64-slice hs} relu(img[n,h]+txtT[h,k]) * W2[h]
// Last-arriving block per n-group sums the 8 partials + b2 -> out, resets counter.
__global__ __launch_bounds__(256) void fused_kernel(
    const float* __restrict__ W2, const float* __restrict__ b2,
    float* __restrict__ part, float* __restrict__ out)
{
    __shared__ __align__(16) float t_s [2][32][128];  // [buf][h][k] 32 KB
    __shared__ __align__(16) u64   a2_s[2][32][32];   // [buf][h][n] (a,a) 16 KB
    __shared__ u64 w2p[64];
    __shared__ unsigned int s_last;

    const int t  = threadIdx.x;
    const int kg = t & 31;
    const int ng = t >> 5;
    const int b  = blockIdx.x;
    const int nb = b & 63;
    const int hs = b >> 6;
    const int hb0 = hs * 64;
    const int nrow0 = nb * 32;

    if (t < 64) { const float w = W2[hb0 + t]; w2p[t] = pack2(w, w); }

    const int tn  = t >> 3;
    const int th4 = t & 7;

    float4 pt[4], pa;
    {
        #pragma unroll
        for (int i = 0; i < 4; i++) {
            const int fid = i * 256 + t;
            const int off = (hb0 + (fid >> 5)) * K_TOK + ((fid & 31) << 2);
            pt[i] = f4add(*(const float4*)&g_txtP[off],
                          *(const float4*)&g_txtP[H_DIM * K_TOK + off]);
        }
        const int aoff = (nrow0 + tn) * H_DIM + hb0 + (th4 << 2);
        pa = f4add(*(const float4*)&g_imgP[aoff],
                   *(const float4*)&g_imgP[N_TOK * H_DIM + aoff]);
    }
    {
        #pragma unroll
        for (int i = 0; i < 4; i++) {
            const int fid = i * 256 + t;
            *(float4*)&t_s[0][fid >> 5][(fid & 31) << 2] = pt[i];
        }
        a2_s[0][(th4 << 2) + 0][tn] = pack2(pa.x, pa.x);
        a2_s[0][(th4 << 2) + 1][tn] = pack2(pa.y, pa.y);
        a2_s[0][(th4 << 2) + 2][tn] = pack2(pa.z, pa.z);
        a2_s[0][(th4 << 2) + 3][tn] = pack2(pa.w, pa.w);
    }
    __syncthreads();

    u64 acc[4][2];
    #pragma unroll
    for (int i = 0; i < 4; i++) { acc[i][0] = 0ull; acc[i][1] = 0ull; }

    for (int c = 0; c < 2; c++) {
        const int buf = c & 1;
        if (c + 1 < 2) {
            const int hbase = hb0 + 32;
            #pragma unroll
            for (int i = 0; i < 4; i++) {
                const int fid = i * 256 + t;
                const int off = (hbase + (fid >> 5)) * K_TOK + ((fid & 31) << 2);
                pt[i] = f4add(*(const float4*)&g_txtP[off],
                              *(const float4*)&g_txtP[H_DIM * K_TOK + off]);
            }
            const int aoff = (nrow0 + tn) * H_DIM + hbase + (th4 << 2);
            pa = f4add(*(const float4*)&g_imgP[aoff],
                       *(const float4*)&g_imgP[N_TOK * H_DIM + aoff]);
        }
        #pragma unroll 8
        for (int h = 0; h < 32; h++) {
            const u64 ww = w2p[c * 32 + h];
            const u64* ap = &a2_s[buf][h][ng << 2];
            const ulonglong2 qa0 = *(const ulonglong2*)(ap + 0);
            const ulonglong2 qa1 = *(const ulonglong2*)(ap + 2);
            const ulonglong2 tq  = *(const ulonglong2*)&t_s[buf][h][kg << 2];
            const u64 av[4] = {qa0.x, qa0.y, qa1.x, qa1.y};
            #pragma unroll
            for (int i = 0; i < 4; i++) {
                fma2(acc[i][0], relu2(add2(av[i], tq.x)), ww);
                fma2(acc[i][1], relu2(add2(av[i], tq.y)), ww);
            }
        }
        if (c + 1 < 2) {
            const int nbuf = buf ^ 1;
            #pragma unroll
            for (int i = 0; i < 4; i++) {
                const int fid = i * 256 + t;
                *(float4*)&t_s[nbuf][fid >> 5][(fid & 31) << 2] = pt[i];
            }
            a2_s[nbuf][(th4 << 2) + 0][tn] = pack2(pa.x, pa.x);
            a2_s[nbuf][(th4 << 2) + 1][tn] = pack2(pa.y, pa.y);
            a2_s[nbuf][(th4 << 2) + 2][tn] = pack2(pa.z, pa.z);
            a2_s[nbuf][(th4 << 2) + 3][tn] = pack2(pa.w, pa.w);
        }
        __syncthreads();
    }

    // write this block's partial
    float* p = part + hs * (N_TOK * K_TOK);
    #pragma unroll
    for (int i = 0; i < 4; i++) {
        const int n = nrow0 + (ng << 2) + i;
        float4 v;
        unpack2(acc[i][0], v.x, v.y);
        unpack2(acc[i][1], v.z, v.w);
        *(float4*)&p[n * K_TOK + (kg << 2)] = v;
    }

    // threadfence reduction: last block for this n-group combines all 8 partials
    __threadfence();
    __syncthreads();
    if (t == 0) {
        const unsigned int old = atomicAdd(&g_cnt[nb], 1u);
        s_last = (old == NSPLIT - 1) ? 1u : 0u;
    }
    __syncthreads();
    if (s_last) {
        // 32 rows x 128 k = 1024 float4, 4 per thread
        const float bb = b2[0];
        #pragma unroll
        for (int i = 0; i < 4; i++) {
            const int e4 = i * 256 + t;                   // float4 index in slice
            const int idx = (nrow0 * K_TOK) + e4 * 4;     // slice is contiguous rows
            float4 v = make_float4(bb, bb, bb, bb);
            #pragma unroll
            for (int s = 0; s < NSPLIT; s++) {
                const float4 q = *(const float4*)&part[s * (N_TOK * K_TOK) + idx];
                v.x += q.x; v.y += q.y; v.z += q.z; v.w += q.w;
            }
            *(float4*)&out[idx] = v;
        }
        if (t == 0) g_cnt[nb] = 0;   // reset for next launch (deterministic replays)
    }
}

extern "C" void kernel_launch(void* const* d_in, const int* in_sizes, int n_in,
                              void* d_out, int out_size) {
    const float* img = (const float*)d_in[0];   // (2048, 768)
    const float* txt = (const float*)d_in[1];   // (128, 768)
    const float* W1  = (const float*)d_in[2];   // (1536, 512)
    const float* b1  = (const float*)d_in[3];   // (512,)
    const float* W2  = (const float*)d_in[4];   // (512, 1)
    const float* b2  = (const float*)d_in[5];   // (1,)
    float* out = (float*)d_out;                 // (2048, 128)

    float* part;
    cudaGetSymbolAddress((void**)&part, g_part);
    cudaFuncSetAttribute(mma_proj, cudaFuncAttributeMaxDynamicSharedMemorySize, PROJ_SMEM);

    conv_AB<<<2400, 256>>>(img, txt, W1);
    mma_proj<<<272, 256, PROJ_SMEM>>>(b1);
    fused_kernel<<<512, 256>>>(W2, b2, part, out);
}

// round 16
// speedup vs baseline: 1.0240x; 1.0240x over previous
#include <cuda_runtime.h>
#include <cuda_bf16.h>
#include <cstdint>

#define N_TOK 2048
#define K_TOK 128
#define D_DIM 768
#define H_DIM 512
#define M_ALL 2176   // 2048 img rows + 128 txt rows
#define NSPLIT 8
#define KSPLIT_D 384 // K per proj split

// ---------------- scratch (device globals; no allocation allowed) ----------------
__device__ __align__(16) __nv_bfloat16 g_Ahi[M_ALL * D_DIM];
__device__ __align__(16) __nv_bfloat16 g_Alo[M_ALL * D_DIM];
__device__ __align__(16) __nv_bfloat16 g_Bhi[2 * H_DIM * D_DIM];  // [half][n][k] = W1^T
__device__ __align__(16) __nv_bfloat16 g_Blo[2 * H_DIM * D_DIM];
__device__ float g_imgP[2 * N_TOK * H_DIM];        // split-K partials [ks][n][h]
__device__ float g_txtP[2 * H_DIM * K_TOK];        // split-K partials [ks][h][k] (+b1 in ks0)
__device__ float g_part[NSPLIT * N_TOK * K_TOK];   // fused h-split partials

typedef unsigned long long u64;

// ---------------- packed f32x2 helpers ----------------
__device__ __forceinline__ u64 pack2(float lo, float hi) {
    u64 r; asm("mov.b64 %0, {%1, %2};" : "=l"(r) : "f"(lo), "f"(hi)); return r;
}
__device__ __forceinline__ void unpack2(u64 v, float& lo, float& hi) {
    asm("mov.b64 {%0, %1}, %2;" : "=f"(lo), "=f"(hi) : "l"(v));
}
__device__ __forceinline__ void fma2(u64& d, u64 a, u64 b) {
    asm("fma.rn.f32x2 %0, %1, %2, %0;" : "+l"(d) : "l"(a), "l"(b));
}
__device__ __forceinline__ u64 add2(u64 a, u64 b) {
    u64 r; asm("add.rn.f32x2 %0, %1, %2;" : "=l"(r) : "l"(a), "l"(b)); return r;
}
__device__ __forceinline__ u64 relu2(u64 v) {
    float lo, hi; unpack2(v, lo, hi);
    return pack2(fmaxf(lo, 0.f), fmaxf(hi, 0.f));
}
__device__ __forceinline__ float4 f4add(float4 a, float4 b) {
    return make_float4(a.x + b.x, a.y + b.y, a.z + b.z, a.w + b.w);
}

// bit-trick hi/lo split for a float PAIR:
//   hip = (trunc-bf16(f0), trunc-bf16(f1)) via one PRMT
//   lop = (rn-bf16(f0-hi0), rn-bf16(f1-hi1)) via one cvt.rn.bf16x2.f32
__device__ __forceinline__ void split2(float f0, float f1, uint32_t& hip, uint32_t& lop) {
    const uint32_t u0 = __float_as_uint(f0), u1 = __float_as_uint(f1);
    const float l0 = f0 - __uint_as_float(u0 & 0xFFFF0000u);
    const float l1 = f1 - __uint_as_float(u1 & 0xFFFF0000u);
    asm("prmt.b32 %0, %1, %2, 0x7632;" : "=r"(hip) : "r"(u0), "r"(u1));
    asm("cvt.rn.bf16x2.f32 %0, %1, %2;" : "=r"(lop) : "f"(l1), "f"(l0));
}

// ---------------- portable HMMA + ldmatrix (plain sm_103 target) ----------------
__device__ __forceinline__ void mma_bf16(float* c, const uint32_t* a, const uint32_t* b) {
    asm("mma.sync.aligned.m16n8k16.row.col.f32.bf16.bf16.f32 "
        "{%0,%1,%2,%3}, {%4,%5,%6,%7}, {%8,%9}, {%0,%1,%2,%3};"
        : "+f"(c[0]), "+f"(c[1]), "+f"(c[2]), "+f"(c[3])
        : "r"(a[0]), "r"(a[1]), "r"(a[2]), "r"(a[3]), "r"(b[0]), "r"(b[1]));
}
__device__ __forceinline__ void ldmat_x4(uint32_t* r, uint32_t addr) {
    asm volatile("ldmatrix.sync.aligned.m8n8.x4.shared.b16 {%0,%1,%2,%3}, [%4];"
        : "=r"(r[0]), "=r"(r[1]), "=r"(r[2]), "=r"(r[3]) : "r"(addr));
}
__device__ __forceinline__ uint32_t smem_u32(const void* p) {
    uint32_t a;
    asm("{ .reg .u64 t; cvta.to.shared.u64 t, %1; cvt.u32.u64 %0, t; }" : "=r"(a) : "l"(p));
    return a;
}

// ============ merged conversion: A (fp32->bf16 hi/lo) + B (transpose + hi/lo) ============
__global__ __launch_bounds__(256) void conv_AB(
    const float* __restrict__ img, const float* __restrict__ txt,
    const float* __restrict__ W1)
{
    __shared__ float ts[32][33];
    if (blockIdx.x < 1632) {
        const int i4 = blockIdx.x * 256 + threadIdx.x;
        const int row = i4 / 192;
        const int col4 = (i4 - row * 192) * 4;
        const float4 v = (row < N_TOK)
            ? *(const float4*)&img[row * D_DIM + col4]
            : *(const float4*)&txt[(row - N_TOK) * D_DIM + col4];
        uint2 hi, lo;
        split2(v.x, v.y, hi.x, lo.x);
        split2(v.z, v.w, hi.y, lo.y);
        const int e = row * D_DIM + col4;
        *(uint2*)(g_Ahi + e) = hi;
        *(uint2*)(g_Alo + e) = lo;
    } else {
        const int bb = blockIdx.x - 1632;            // 0..767
        const int half = bb / 384;
        const int k0 = ((bb - half * 384) >> 4) * 32;
        const int n0 = (bb & 15) * 32;
        const float* __restrict__ W = W1 + half * (D_DIM * H_DIM);
        const int r  = threadIdx.x >> 3;
        const int c4 = (threadIdx.x & 7) * 4;
        const float4 v = *(const float4*)&W[(k0 + r) * H_DIM + n0 + c4];
        ts[r][c4 + 0] = v.x; ts[r][c4 + 1] = v.y; ts[r][c4 + 2] = v.z; ts[r][c4 + 3] = v.w;
        __syncthreads();
        uint2 hi, lo;
        split2(ts[c4 + 0][r], ts[c4 + 1][r], hi.x, lo.x);
        split2(ts[c4 + 2][r], ts[c4 + 3][r], hi.y, lo.y);
        const int e = half * (H_DIM * D_DIM) + (n0 + r) * D_DIM + k0 + c4;
        *(uint2*)(g_Bhi + e) = hi;
        *(uint2*)(g_Blo + e) = lo;
    }
}

// ============ HMMA projection GEMM — split-K x2, 2 CTAs/SM ============
#define KC 32
#define A_ROWSTRIDE 80           // bytes (40 bf16)
#define A_BUFSTRIDE (128 * 80)   // 10240
#define B_BUFSTRIDE (64 * 80)    // 5120
#define OFF_AHI 0
#define OFF_ALO 20480
#define OFF_BHI 40960
#define OFF_BLO 51200
#define PROJ_SMEM 61440

__global__ __launch_bounds__(256, 2) void mma_proj(const float* __restrict__ b1)
{
    extern __shared__ char smem[];
    const uint32_t sb = smem_u32(smem);

    const int t    = threadIdx.x;
    const int lane = t & 31;
    const int warp = t >> 5;
    const int wm   = warp >> 1;
    const int wn   = warp & 1;
    const int g    = lane >> 2;
    const int t2   = (lane & 3) << 1;

    const int a_lrow = lane & 15;
    const int a_k16  = (lane >> 4) << 4;
    const int b_lrow = (lane & 7) + ((lane >> 4) << 3);
    const int b_k16  = ((lane >> 3) & 1) << 4;

    const int tile = blockIdx.x >> 1;
    const int ks   = blockIdx.x & 1;
    const int kofs = ks * KSPLIT_D;
    const int mt = tile >> 3, nt = tile & 7;
    const int m0 = mt * 128, n0 = nt * 64;
    const bool is_txt = (mt == 16);
    const __nv_bfloat16* __restrict__ Bh = g_Bhi + (is_txt ? H_DIM * D_DIM : 0);
    const __nv_bfloat16* __restrict__ Bl = g_Blo + (is_txt ? H_DIM * D_DIM : 0);

    const int arow0 = t >> 2,           abyte0 = (t & 3) << 4;
    const int arow1 = (t + 256) >> 2,   abyte1 = abyte0;
    const int brow  = t >> 2,           bbyte  = (t & 3) << 4;
    const int eA0 = (m0 + arow0) * D_DIM + kofs + (abyte0 >> 1);
    const int eA1 = (m0 + arow1) * D_DIM + kofs + (abyte1 >> 1);
    const int eB  = (n0 + brow) * D_DIM + kofs + (bbyte >> 1);

    float acc[2][4][4];
    #pragma unroll
    for (int i = 0; i < 2; i++)
        #pragma unroll
        for (int j = 0; j < 4; j++)
            #pragma unroll
            for (int p = 0; p < 4; p++) acc[i][j][p] = 0.f;

    {
        *(float4*)(smem + OFF_AHI + arow0 * A_ROWSTRIDE + abyte0) = *(const float4*)(g_Ahi + eA0);
        *(float4*)(smem + OFF_AHI + arow1 * A_ROWSTRIDE + abyte1) = *(const float4*)(g_Ahi + eA1);
        *(float4*)(smem + OFF_ALO + arow0 * A_ROWSTRIDE + abyte0) = *(const float4*)(g_Alo + eA0);
        *(float4*)(smem + OFF_ALO + arow1 * A_ROWSTRIDE + abyte1) = *(const float4*)(g_Alo + eA1);
        *(float4*)(smem + OFF_BHI + brow * A_ROWSTRIDE + bbyte)   = *(const float4*)(Bh + eB);
        *(float4*)(smem + OFF_BLO + brow * A_ROWSTRIDE + bbyte)   = *(const float4*)(Bl + eB);
    }
    __syncthreads();

    const int NCHUNK = KSPLIT_D / KC;  // 12
    for (int kc = 0; kc < NCHUNK; kc++) {
        const int buf = kc & 1;

        float4 vah0, vah1, val0, val1, vbh, vbl;
        if (kc + 1 < NCHUNK) {
            const int k0 = (kc + 1) * KC;
            vah0 = *(const float4*)(g_Ahi + eA0 + k0);
            vah1 = *(const float4*)(g_Ahi + eA1 + k0);
            val0 = *(const float4*)(g_Alo + eA0 + k0);
            val1 = *(const float4*)(g_Alo + eA1 + k0);
            vbh  = *(const float4*)(Bh + eB + k0);
            vbl  = *(const float4*)(Bl + eB + k0);
        }

        const uint32_t aHiBase = sb + OFF_AHI + buf * A_BUFSTRIDE;
        const uint32_t bHiBase = sb + OFF_BHI + buf * B_BUFSTRIDE;

        #pragma unroll
        for (int kk = 0; kk < 2; kk++) {
            const int kbb = kk * 32;
            uint32_t ah[2][4], al[2][4], bh[2][4], bl[2][4];
            #pragma unroll
            for (int ma = 0; ma < 2; ma++) {
                const uint32_t ra = aHiBase
                    + (uint32_t)((wm * 32 + ma * 16 + a_lrow) * A_ROWSTRIDE + kbb + a_k16);
                ldmat_x4(ah[ma], ra);
                ldmat_x4(al[ma], ra + (OFF_ALO - OFF_AHI));
            }
            #pragma unroll
            for (int np = 0; np < 2; np++) {
                const uint32_t rb = bHiBase
                    + (uint32_t)((wn * 32 + np * 16 + b_lrow) * A_ROWSTRIDE + kbb + b_k16);
                ldmat_x4(bh[np], rb);
                ldmat_x4(bl[np], rb + (OFF_BLO - OFF_BHI));
            }
            #pragma unroll
            for (int ma = 0; ma < 2; ma++)
                #pragma unroll
                for (int na = 0; na < 4; na++) {
                    const uint32_t* bhp = &bh[na >> 1][(na & 1) * 2];
                    const uint32_t* blp = &bl[na >> 1][(na & 1) * 2];
                    mma_bf16(acc[ma][na], ah[ma], bhp);
                    mma_bf16(acc[ma][na], ah[ma], blp);
                    mma_bf16(acc[ma][na], al[ma], bhp);
                }
        }

        if (kc + 1 < NCHUNK) {
            const int so = (buf ^ 1);
            *(float4*)(smem + OFF_AHI + so * A_BUFSTRIDE + arow0 * A_ROWSTRIDE + abyte0) = vah0;
            *(float4*)(smem + OFF_AHI + so * A_BUFSTRIDE + arow1 * A_ROWSTRIDE + abyte1) = vah1;
            *(float4*)(smem + OFF_ALO + so * A_BUFSTRIDE + arow0 * A_ROWSTRIDE + abyte0) = val0;
            *(float4*)(smem + OFF_ALO + so * A_BUFSTRIDE + arow1 * A_ROWSTRIDE + abyte1) = val1;
            *(float4*)(smem + OFF_BHI + so * B_BUFSTRIDE + brow * A_ROWSTRIDE + bbyte) = vbh;
            *(float4*)(smem + OFF_BLO + so * B_BUFSTRIDE + brow * A_ROWSTRIDE + bbyte) = vbl;
        }
        __syncthreads();
    }

    float* imgP = g_imgP + ks * (N_TOK * H_DIM);
    float* txtP = g_txtP + ks * (H_DIM * K_TOK);
    #pragma unroll
    for (int ma = 0; ma < 2; ma++) {
        const int lr0 = wm * 32 + ma * 16 + g;
        #pragma unroll
        for (int na = 0; na < 4; na++) {
            const int n = n0 + wn * 32 + na * 8 + t2;
            if (!is_txt) {
                *(float2*)&imgP[(m0 + lr0) * H_DIM + n] =
                    make_float2(acc[ma][na][0], acc[ma][na][1]);
                *(float2*)&imgP[(m0 + lr0 + 8) * H_DIM + n] =
                    make_float2(acc[ma][na][2], acc[ma][na][3]);
            } else {
                const float bb0 = ks ? 0.f : __ldg(&b1[n]);
                const float bb1 = ks ? 0.f : __ldg(&b1[n + 1]);
                txtP[n * K_TOK + lr0]           = acc[ma][na][0] + bb0;
                txtP[(n + 1) * K_TOK + lr0]     = acc[ma][na][1] + bb1;
                txtP[n * K_TOK + lr0 + 8]       = acc[ma][na][2] + bb0;
                txtP[(n + 1) * K_TOK + lr0 + 8] = acc[ma][na][3] + bb1;
            }
        }
    }
}

// ============ fused relu-dot, 8-way h-split (sums split-K partials in loaders) ============
__global__ __launch_bounds__(256) void fused_kernel(
    const float* __restrict__ W2, float* __restrict__ part)
{
    __shared__ __align__(16) float t_s [2][32][128];  // [buf][h][k] 32 KB
    __shared__ __align__(16) u64   a2_s[2][32][32];   // [buf][h][n] (a,a) 16 KB
    __shared__ u64 w2p[64];

    const int t  = threadIdx.x;
    const int kg = t & 31;
    const int ng = t >> 5;
    const int b  = blockIdx.x;
    const int nb = b & 63;
    const int hs = b >> 6;
    const int hb0 = hs * 64;
    const int nrow0 = nb * 32;

    if (t < 64) { const float w = W2[hb0 + t]; w2p[t] = pack2(w, w); }

    const int tn  = t >> 3;
    const int th4 = t & 7;

    float4 pt[4], pa;
    {
        #pragma unroll
        for (int i = 0; i < 4; i++) {
            const int fid = i * 256 + t;
            const int off = (hb0 + (fid >> 5)) * K_TOK + ((fid & 31) << 2);
            pt[i] = f4add(*(const float4*)&g_txtP[off],
                          *(const float4*)&g_txtP[H_DIM * K_TOK + off]);
        }
        const int aoff = (nrow0 + tn) * H_DIM + hb0 + (th4 << 2);
        pa = f4add(*(const float4*)&g_imgP[aoff],
                   *(const float4*)&g_imgP[N_TOK * H_DIM + aoff]);
    }
    {
        #pragma unroll
        for (int i = 0; i < 4; i++) {
            const int fid = i * 256 + t;
            *(float4*)&t_s[0][fid >> 5][(fid & 31) << 2] = pt[i];
        }
        a2_s[0][(th4 << 2) + 0][tn] = pack2(pa.x, pa.x);
        a2_s[0][(th4 << 2) + 1][tn] = pack2(pa.y, pa.y);
        a2_s[0][(th4 << 2) + 2][tn] = pack2(pa.z, pa.z);
        a2_s[0][(th4 << 2) + 3][tn] = pack2(pa.w, pa.w);
    }
    __syncthreads();

    u64 acc[4][2];
    #pragma unroll
    for (int i = 0; i < 4; i++) { acc[i][0] = 0ull; acc[i][1] = 0ull; }

    for (int c = 0; c < 2; c++) {
        const int buf = c & 1;
        if (c + 1 < 2) {
            const int hbase = hb0 + 32;
            #pragma unroll
            for (int i = 0; i < 4; i++) {
                const int fid = i * 256 + t;
                const int off = (hbase + (fid >> 5)) * K_TOK + ((fid & 31) << 2);
                pt[i] = f4add(*(const float4*)&g_txtP[off],
                              *(const float4*)&g_txtP[H_DIM * K_TOK + off]);
            }
            const int aoff = (nrow0 + tn) * H_DIM + hbase + (th4 << 2);
            pa = f4add(*(const float4*)&g_imgP[aoff],
                       *(const float4*)&g_imgP[N_TOK * H_DIM + aoff]);
        }
        #pragma unroll 8
        for (int h = 0; h < 32; h++) {
            const u64 ww = w2p[c * 32 + h];
            const u64* ap = &a2_s[buf][h][ng << 2];
            const ulonglong2 qa0 = *(const ulonglong2*)(ap + 0);
            const ulonglong2 qa1 = *(const ulonglong2*)(ap + 2);
            const ulonglong2 tq  = *(const ulonglong2*)&t_s[buf][h][kg << 2];
            const u64 av[4] = {qa0.x, qa0.y, qa1.x, qa1.y};
            #pragma unroll
            for (int i = 0; i < 4; i++) {
                fma2(acc[i][0], relu2(add2(av[i], tq.x)), ww);
                fma2(acc[i][1], relu2(add2(av[i], tq.y)), ww);
            }
        }
        if (c + 1 < 2) {
            const int nbuf = buf ^ 1;
            #pragma unroll
            for (int i = 0; i < 4; i++) {
                const int fid = i * 256 + t;
                *(float4*)&t_s[nbuf][fid >> 5][(fid & 31) << 2] = pt[i];
            }
            a2_s[nbuf][(th4 << 2) + 0][tn] = pack2(pa.x, pa.x);
            a2_s[nbuf][(th4 << 2) + 1][tn] = pack2(pa.y, pa.y);
            a2_s[nbuf][(th4 << 2) + 2][tn] = pack2(pa.z, pa.z);
            a2_s[nbuf][(th4 << 2) + 3][tn] = pack2(pa.w, pa.w);
        }
        __syncthreads();
    }

    float* p = part + hs * (N_TOK * K_TOK);
    #pragma unroll
    for (int i = 0; i < 4; i++) {
        const int n = nrow0 + (ng << 2) + i;
        float4 v;
        unpack2(acc[i][0], v.x, v.y);
        unpack2(acc[i][1], v.z, v.w);
        *(float4*)&p[n * K_TOK + (kg << 2)] = v;
    }
}

// ============ combine: out = sum of 8 partials + b2 ============
__global__ __launch_bounds__(256) void combine_kernel(
    const float* __restrict__ b2, float* __restrict__ out)
{
    const int idx = (blockIdx.x * 256 + threadIdx.x) * 4;
    float4 v = make_float4(b2[0], b2[0], b2[0], b2[0]);
    #pragma unroll
    for (int s = 0; s < NSPLIT; s++) {
        const float4 p = *(const float4*)&g_part[s * (N_TOK * K_TOK) + idx];
        v.x += p.x; v.y += p.y; v.z += p.z; v.w += p.w;
    }
    *(float4*)&out[idx] = v;
}

extern "C" void kernel_launch(void* const* d_in, const int* in_sizes, int n_in,
                              void* d_out, int out_size) {
    const float* img = (const float*)d_in[0];   // (2048, 768)
    const float* txt = (const float*)d_in[1];   // (128, 768)
    const float* W1  = (const float*)d_in[2];   // (1536, 512)
    const float* b1  = (const float*)d_in[3];   // (512,)
    const float* W2  = (const float*)d_in[4];   // (512, 1)
    const float* b2  = (const float*)d_in[5];   // (1,)
    float* out = (float*)d_out;                 // (2048, 128)

    float* part;
    cudaGetSymbolAddress((void**)&part, g_part);
    cudaFuncSetAttribute(mma_proj, cudaFuncAttributeMaxDynamicSharedMemorySize, PROJ_SMEM);

    conv_AB<<<2400, 256>>>(img, txt, W1);
    mma_proj<<<272, 256, PROJ_SMEM>>>(b1);
    fused_kernel<<<512, 256>>>(W2, part);
    combine_kernel<<<(N_TOK * K_TOK) / (256 * 4), 256>>>(b2, out);
}